// round 1
// baseline (speedup 1.0000x reference)
#include <cuda_runtime.h>
#include <math.h>

#define B 8
#define S 8192
#define H 256
#define M 64
#define HM 128
#define KC 8   // split-K chunks in the DFT

// ---------------- scratch (device globals, no allocation) ----------------
__device__ float2 g_basis[S * M];            // [t][m] -> (cos, sin) of 2*pi*m*t/S   (4 MB)
__device__ float  g_utr[B * M * H];
__device__ float  g_uti[B * M * H];
__device__ float  g_sr [B * M * H];
__device__ float  g_si [B * M * H];
__device__ float  g_cvr[B * M * H];          // conv real, pre-scaled by 1/(8*8192)
__device__ float  g_cvi[B * M * H];
__device__ float  g_part[B * 4 * KC * 2 * 4096];   // DFT split-K partials (8 MB)

// ---------------- helpers ----------------
__device__ __forceinline__ void fma2(float2 &d, float2 a, float2 b) {
    // packed fp32x2 FMA (sm_100+): d.x += a.x*b.x ; d.y += a.y*b.y
    asm("fma.rn.f32x2 %0, %1, %2, %0;"
        : "+l"(*reinterpret_cast<unsigned long long *>(&d))
        : "l"(*reinterpret_cast<unsigned long long *>(&a)),
          "l"(*reinterpret_cast<unsigned long long *>(&b)));
}

__device__ __forceinline__ float gelu(float x) {
    return 0.5f * x * (1.0f + erff(x * 0.70710678118654752f));
}

// ---------------- K0: basis table ----------------
__global__ void k_basis() {
    int idx = blockIdx.x * 256 + threadIdx.x;
    if (idx >= S * M) return;
    int t = idx >> 6, m = idx & 63;
    int ph = (m * t) & (S - 1);                     // exact phase mod S
    float ang = (float)ph * (6.283185307179586f / 8192.0f);
    float sn, cn;
    sincosf(ang, &sn, &cn);
    g_basis[idx] = make_float2(cn, sn);
}

// ---------------- K1: DFT split-K  ut_partial[b,ht,kc][m][h64] ----------------
__global__ void __launch_bounds__(256) k_dft(const float *__restrict__ u) {
    __shared__ __align__(16) float2 u2s[16][32];   // 16 t-rows x 32 h-pairs
    __shared__ __align__(16) float2 bss[16][64];   // 16 t-rows x 64 modes (cos,sin)
    int b = blockIdx.x, ht = blockIdx.y, kc = blockIdx.z;
    int tid = threadIdx.x;
    int m0  = (tid >> 4) << 2;          // 4 modes per thread
    int hp0 = (tid & 15) << 1;          // 2 float2 (=4 h) per thread
    int h0  = ht * 64;

    float2 ar[4][2], ai[4][2];
#pragma unroll
    for (int i = 0; i < 4; i++)
#pragma unroll
        for (int j = 0; j < 2; j++) { ar[i][j] = make_float2(0.f, 0.f); ai[i][j] = make_float2(0.f, 0.f); }

    const float2 *u2 = (const float2 *)u;
    int tstart = kc * 1024;
    for (int tc = 0; tc < 1024; tc += 16) {
        int tbase = tstart + tc;
#pragma unroll
        for (int i = 0; i < 2; i++) {
            int lin = i * 256 + tid; int tt = lin >> 5, hp = lin & 31;
            u2s[tt][hp] = u2[(size_t)(b * S + tbase + tt) * 128 + (h0 >> 1) + hp];
        }
#pragma unroll
        for (int i = 0; i < 4; i++) {
            int lin = i * 256 + tid; int tt = lin >> 6, m = lin & 63;
            bss[tt][m] = g_basis[(tbase + tt) * 64 + m];
        }
        __syncthreads();
#pragma unroll
        for (int tt = 0; tt < 16; tt++) {
            float2 uu0 = u2s[tt][hp0], uu1 = u2s[tt][hp0 + 1];
#pragma unroll
            for (int im = 0; im < 4; im++) {
                float2 cs = bss[tt][m0 + im];
                float2 cc = make_float2(cs.x, cs.x);
                float2 ns = make_float2(-cs.y, -cs.y);     // e^{-i}: imag -= u*sin
                fma2(ar[im][0], uu0, cc); fma2(ai[im][0], uu0, ns);
                fma2(ar[im][1], uu1, cc); fma2(ai[im][1], uu1, ns);
            }
        }
        __syncthreads();
    }
    float2 *pr = (float2 *)&g_part[(size_t)((b * 4 + ht) * KC + kc) * 8192];
    float2 *pi = pr + 2048;   // imag component +4096 floats
#pragma unroll
    for (int im = 0; im < 4; im++)
#pragma unroll
        for (int j = 0; j < 2; j++) {
            pr[(m0 + im) * 32 + hp0 + j] = ar[im][j];
            pi[(m0 + im) * 32 + hp0 + j] = ai[im][j];
        }
}

// ---------------- K1b: reduce split-K ----------------
__global__ void k_red() {
    int gid = blockIdx.x * 256 + threadIdx.x;
    if (gid >= B * M * H) return;
    int h = gid & 255, m = (gid >> 8) & 63, b = gid >> 14;
    int ht = h >> 6, hh = h & 63;
    float sr = 0.f, si = 0.f;
#pragma unroll
    for (int kc = 0; kc < KC; kc++) {
        const float *p = &g_part[(size_t)((b * 4 + ht) * KC + kc) * 8192 + m * 64 + hh];
        sr += p[0]; si += p[4096];
    }
    g_utr[gid] = sr; g_uti[gid] = si;
}

// ---------------- K2: per-mode complex GEMM + GELU epilogue -> s ----------------
__global__ void __launch_bounds__(256) k_modegemm(const float *__restrict__ Wr,
                                                  const float *__restrict__ Wi) {
    __shared__ float utr_s[8][256];
    __shared__ float uti_s[8][256];
    int m = blockIdx.x, half = blockIdx.y;
    int tid = threadIdx.x;
#pragma unroll
    for (int i = 0; i < 8; i++) {
        int lin = i * 256 + tid; int bb = lin >> 8, h = lin & 255;
        utr_s[bb][h] = g_utr[(bb * 64 + m) * 256 + h];
        uti_s[bb][h] = g_uti[(bb * 64 + m) * 256 + h];
    }
    __syncthreads();
    int ho = half * 128 + (tid & 127);
    int bg = (tid >> 7) * 4;
    float accr[4] = {0.f, 0.f, 0.f, 0.f}, acci[4] = {0.f, 0.f, 0.f, 0.f};
    const float *wrp = Wr + (size_t)m * 65536 + ho;
    const float *wip = Wi + (size_t)m * 65536 + ho;
#pragma unroll 4
    for (int hk = 0; hk < 256; hk++) {
        float wr = wrp[(size_t)hk * 256], wi = wip[(size_t)hk * 256];
#pragma unroll
        for (int ib = 0; ib < 4; ib++) {
            float ur = utr_s[bg + ib][hk], ui = uti_s[bg + ib][hk];
            accr[ib] += ur * wr - ui * wi;
            acci[ib] += ur * wi + ui * wr;
        }
    }
#pragma unroll
    for (int ib = 0; ib < 4; ib++) {
        int o = ((bg + ib) * 64 + m) * 256 + ho;
        g_sr[o] = gelu(accr[ib]);
        g_si[o] = gelu(acci[ib]);
    }
}

// ---------------- K3: length-64 complex circular convolution ----------------
__global__ void __launch_bounds__(256) k_conv() {
    __shared__ __align__(16) float utr_s[64][32];
    __shared__ __align__(16) float uti_s[64][32];
    __shared__ __align__(16) float sr_s[64][32];
    __shared__ __align__(16) float si_s[64][32];
    int b = blockIdx.x, ht = blockIdx.y;     // ht: 8 tiles of 32 h
    int h0 = ht * 32;
    int tid = threadIdx.x;
#pragma unroll
    for (int i = 0; i < 8; i++) {
        int lin = i * 256 + tid; int k = lin >> 5, hh = lin & 31;
        int o = (b * 64 + k) * 256 + h0 + hh;
        utr_s[k][hh] = g_utr[o]; uti_s[k][hh] = g_uti[o];
        sr_s[k][hh]  = g_sr[o];  si_s[k][hh]  = g_si[o];
    }
    __syncthreads();
    int m0 = (tid >> 4) << 2;     // 4 modes
    int hp = tid & 15;            // 1 float2 (2 h)
    float2 cr[4], ci[4];
#pragma unroll
    for (int i = 0; i < 4; i++) { cr[i] = make_float2(0.f, 0.f); ci[i] = make_float2(0.f, 0.f); }
    for (int k = 0; k < 64; k++) {
        float2 ua = ((float2 *)utr_s[k])[hp];
        float2 ub = ((float2 *)uti_s[k])[hp];
#pragma unroll
        for (int im = 0; im < 4; im++) {
            int j = ((m0 + im) - k) & 63;
            float2 br = ((float2 *)sr_s[j])[hp];
            float2 bi = ((float2 *)si_s[j])[hp];
            float2 nbi = make_float2(-bi.x, -bi.y);
            fma2(cr[im], ua, br);  fma2(cr[im], ub, nbi);
            fma2(ci[im], ua, bi);  fma2(ci[im], ub, br);
        }
    }
    const float SC = 1.0f / 65536.0f;   // (1/8 from sqrt(M)) * (1/8192 from final ifft)
#pragma unroll
    for (int im = 0; im < 4; im++) {
        int o = (b * 64 + m0 + im) * 256 + h0 + 2 * hp;
        *(float2 *)&g_cvr[o] = make_float2(cr[im].x * SC, cr[im].y * SC);
        *(float2 *)&g_cvi[o] = make_float2(ci[im].x * SC, ci[im].y * SC);
    }
}

// ---------------- K4: fused iDFT + skip GEMM + GELU + MLP ----------------
// dynamic smem layout (floats):
//   A  [32][258]  : u tile, then activated tile        (8256)
//   W  [32][258]  : weight staging chunk               (8256)
//   BS [32][64]   : basis (cos,sin) float2             (4096 floats)
//   HMs[32][132]  : hidden MLP tile                    (4224)
#define SM_A  0
#define SM_W  8256
#define SM_BS 16512
#define SM_HM 20608
#define SMEM_FLOATS 24832
#define SMEM_BYTES (SMEM_FLOATS * 4)

__global__ void __launch_bounds__(256, 2) k_final(
    const float *__restrict__ u,  const float *__restrict__ skw,
    const float *__restrict__ skb, const float *__restrict__ w1,
    const float *__restrict__ b1,  const float *__restrict__ w2,
    const float *__restrict__ b2,  float *__restrict__ out) {
    extern __shared__ __align__(16) float smem[];
    float  *A  = smem + SM_A;
    float  *W  = smem + SM_W;
    float2 *BS = (float2 *)(smem + SM_BS);
    float  *HMs = smem + SM_HM;

    int t0 = blockIdx.x * 32;
    int b  = blockIdx.y;
    int tid = threadIdx.x;
    int r0 = (tid >> 5) << 2;         // 4 rows
    int c0 = (tid & 31) << 3;         // 8 cols (4 float2)
    int c1 = (tid & 31) << 2;         // 4 cols for 128-wide mid layer

    // stage basis rows for this t-tile
#pragma unroll
    for (int i = 0; i < 8; i++) {
        int lin = i * 256 + tid; int r = lin >> 6, m = lin & 63;
        BS[r * 64 + m] = g_basis[(t0 + r) * 64 + m];
    }
    // stage u tile
    const float2 *u2 = (const float2 *)u;
#pragma unroll
    for (int i = 0; i < 16; i++) {
        int lin = i * 256 + tid; int r = lin >> 7, kp = lin & 127;
        *(float2 *)&A[r * 258 + kp * 2] = u2[(size_t)(b * S + t0 + r) * 128 + kp];
    }
    __syncthreads();

    float2 acc[4][4];
#pragma unroll
    for (int i = 0; i < 4; i++)
#pragma unroll
        for (int j = 0; j < 4; j++) acc[i][j] = make_float2(0.f, 0.f);

    // ---- (a) conv_sp: 64-mode inverse DFT (conv already scaled) ----
    for (int m = 0; m < 64; m++) {
        const float2 *crp = (const float2 *)&g_cvr[(b * 64 + m) * 256];
        const float2 *cip = (const float2 *)&g_cvi[(b * 64 + m) * 256];
        float2 cv[4], civ[4];
#pragma unroll
        for (int jj = 0; jj < 4; jj++) { cv[jj] = crp[(c0 >> 1) + jj]; civ[jj] = cip[(c0 >> 1) + jj]; }
#pragma unroll
        for (int i = 0; i < 4; i++) {
            float2 cs = BS[(r0 + i) * 64 + m];
            float2 cc = make_float2(cs.x, cs.x);
            float2 ns = make_float2(-cs.y, -cs.y);     // Re(conv * e^{+i}) = cr*cos - ci*sin
#pragma unroll
            for (int jj = 0; jj < 4; jj++) { fma2(acc[i][jj], cv[jj], cc); fma2(acc[i][jj], civ[jj], ns); }
        }
    }

    // ---- (b) skip GEMM: acc += u @ skip_w^T ----
    for (int kc = 0; kc < 8; kc++) {
#pragma unroll
        for (int i = 0; i < 32; i++) {
            int lin = i * 256 + tid; int j = lin >> 5, kl = lin & 31;
            W[kl * 258 + j] = skw[j * 256 + kc * 32 + kl];
        }
        __syncthreads();
#pragma unroll 4
        for (int kl = 0; kl < 32; kl++) {
            float a0 = A[(r0 + 0) * 258 + kc * 32 + kl];
            float a1 = A[(r0 + 1) * 258 + kc * 32 + kl];
            float a2 = A[(r0 + 2) * 258 + kc * 32 + kl];
            float a3 = A[(r0 + 3) * 258 + kc * 32 + kl];
            const float *wrow = &W[kl * 258 + c0];
            float2 bv0 = *(const float2 *)&wrow[0];
            float2 bv1 = *(const float2 *)&wrow[2];
            float2 bv2 = *(const float2 *)&wrow[4];
            float2 bv3 = *(const float2 *)&wrow[6];
            float2 aa;
            aa = make_float2(a0, a0); fma2(acc[0][0], aa, bv0); fma2(acc[0][1], aa, bv1); fma2(acc[0][2], aa, bv2); fma2(acc[0][3], aa, bv3);
            aa = make_float2(a1, a1); fma2(acc[1][0], aa, bv0); fma2(acc[1][1], aa, bv1); fma2(acc[1][2], aa, bv2); fma2(acc[1][3], aa, bv3);
            aa = make_float2(a2, a2); fma2(acc[2][0], aa, bv0); fma2(acc[2][1], aa, bv1); fma2(acc[2][2], aa, bv2); fma2(acc[2][3], aa, bv3);
            aa = make_float2(a3, a3); fma2(acc[3][0], aa, bv0); fma2(acc[3][1], aa, bv1); fma2(acc[3][2], aa, bv2); fma2(acc[3][3], aa, bv3);
        }
        __syncthreads();
    }

    // ---- (c) bias + GELU -> activated tile into A ----
    float2 sb[4];
#pragma unroll
    for (int jj = 0; jj < 4; jj++) sb[jj] = *(const float2 *)&skb[c0 + 2 * jj];
#pragma unroll
    for (int i = 0; i < 4; i++)
#pragma unroll
        for (int jj = 0; jj < 4; jj++) {
            float x = acc[i][jj].x + sb[jj].x;
            float y = acc[i][jj].y + sb[jj].y;
            *(float2 *)&A[(r0 + i) * 258 + c0 + 2 * jj] = make_float2(gelu(x), gelu(y));
        }
    __syncthreads();

    // ---- (d) MLP1: h = gelu(act @ w1^T + b1) ----
    float2 h2[4][2];
#pragma unroll
    for (int i = 0; i < 4; i++) { h2[i][0] = make_float2(0.f, 0.f); h2[i][1] = make_float2(0.f, 0.f); }
    for (int kc = 0; kc < 8; kc++) {
#pragma unroll
        for (int i = 0; i < 16; i++) {
            int lin = i * 256 + tid; int j = lin >> 5, kl = lin & 31;   // j < 128
            W[kl * 258 + j] = w1[j * 256 + kc * 32 + kl];
        }
        __syncthreads();
#pragma unroll 4
        for (int kl = 0; kl < 32; kl++) {
            float a0 = A[(r0 + 0) * 258 + kc * 32 + kl];
            float a1 = A[(r0 + 1) * 258 + kc * 32 + kl];
            float a2 = A[(r0 + 2) * 258 + kc * 32 + kl];
            float a3 = A[(r0 + 3) * 258 + kc * 32 + kl];
            const float *wrow = &W[kl * 258 + c1];
            float2 bv0 = *(const float2 *)&wrow[0];
            float2 bv1 = *(const float2 *)&wrow[2];
            float2 aa;
            aa = make_float2(a0, a0); fma2(h2[0][0], aa, bv0); fma2(h2[0][1], aa, bv1);
            aa = make_float2(a1, a1); fma2(h2[1][0], aa, bv0); fma2(h2[1][1], aa, bv1);
            aa = make_float2(a2, a2); fma2(h2[2][0], aa, bv0); fma2(h2[2][1], aa, bv1);
            aa = make_float2(a3, a3); fma2(h2[3][0], aa, bv0); fma2(h2[3][1], aa, bv1);
        }
        __syncthreads();
    }
    float2 b1v0 = *(const float2 *)&b1[c1];
    float2 b1v1 = *(const float2 *)&b1[c1 + 2];
#pragma unroll
    for (int i = 0; i < 4; i++) {
        float2 v0 = make_float2(gelu(h2[i][0].x + b1v0.x), gelu(h2[i][0].y + b1v0.y));
        float2 v1 = make_float2(gelu(h2[i][1].x + b1v1.x), gelu(h2[i][1].y + b1v1.y));
        *(float2 *)&HMs[(r0 + i) * 132 + c1]     = v0;
        *(float2 *)&HMs[(r0 + i) * 132 + c1 + 2] = v1;
    }
    __syncthreads();

    // ---- (e) MLP2: out = h @ w2^T + b2 ----
#pragma unroll
    for (int i = 0; i < 4; i++)
#pragma unroll
        for (int j = 0; j < 4; j++) acc[i][j] = make_float2(0.f, 0.f);
    for (int kc = 0; kc < 4; kc++) {
#pragma unroll
        for (int i = 0; i < 32; i++) {
            int lin = i * 256 + tid; int j = lin >> 5, kl = lin & 31;   // j < 256, k < 128
            W[kl * 258 + j] = w2[j * 128 + kc * 32 + kl];
        }
        __syncthreads();
#pragma unroll 4
        for (int kl = 0; kl < 32; kl++) {
            float a0 = HMs[(r0 + 0) * 132 + kc * 32 + kl];
            float a1 = HMs[(r0 + 1) * 132 + kc * 32 + kl];
            float a2 = HMs[(r0 + 2) * 132 + kc * 32 + kl];
            float a3 = HMs[(r0 + 3) * 132 + kc * 32 + kl];
            const float *wrow = &W[kl * 258 + c0];
            float2 bv0 = *(const float2 *)&wrow[0];
            float2 bv1 = *(const float2 *)&wrow[2];
            float2 bv2 = *(const float2 *)&wrow[4];
            float2 bv3 = *(const float2 *)&wrow[6];
            float2 aa;
            aa = make_float2(a0, a0); fma2(acc[0][0], aa, bv0); fma2(acc[0][1], aa, bv1); fma2(acc[0][2], aa, bv2); fma2(acc[0][3], aa, bv3);
            aa = make_float2(a1, a1); fma2(acc[1][0], aa, bv0); fma2(acc[1][1], aa, bv1); fma2(acc[1][2], aa, bv2); fma2(acc[1][3], aa, bv3);
            aa = make_float2(a2, a2); fma2(acc[2][0], aa, bv0); fma2(acc[2][1], aa, bv1); fma2(acc[2][2], aa, bv2); fma2(acc[2][3], aa, bv3);
            aa = make_float2(a3, a3); fma2(acc[3][0], aa, bv0); fma2(acc[3][1], aa, bv1); fma2(acc[3][2], aa, bv2); fma2(acc[3][3], aa, bv3);
        }
        __syncthreads();
    }
    float2 *out2 = (float2 *)out;
    float2 bo[4];
#pragma unroll
    for (int jj = 0; jj < 4; jj++) bo[jj] = *(const float2 *)&b2[c0 + 2 * jj];
#pragma unroll
    for (int i = 0; i < 4; i++)
#pragma unroll
        for (int jj = 0; jj < 4; jj++) {
            float2 v = make_float2(acc[i][jj].x + bo[jj].x, acc[i][jj].y + bo[jj].y);
            out2[(size_t)(b * S + t0 + r0 + i) * 128 + (c0 >> 1) + jj] = v;
        }
}

// ---------------- launch ----------------
extern "C" void kernel_launch(void *const *d_in, const int *in_sizes, int n_in,
                              void *d_out, int out_size) {
    const float *u   = (const float *)d_in[0];
    const float *Wr  = (const float *)d_in[1];
    const float *Wi  = (const float *)d_in[2];
    const float *skw = (const float *)d_in[3];
    const float *skb = (const float *)d_in[4];
    const float *w1  = (const float *)d_in[5];
    const float *b1  = (const float *)d_in[6];
    const float *w2  = (const float *)d_in[7];
    const float *b2  = (const float *)d_in[8];
    float *out = (float *)d_out;

    cudaFuncSetAttribute(k_final, cudaFuncAttributeMaxDynamicSharedMemorySize, SMEM_BYTES);

    k_basis<<<(S * M + 255) / 256, 256>>>();
    k_dft<<<dim3(B, 4, KC), 256>>>(u);
    k_red<<<(B * M * H + 255) / 256, 256>>>();
    k_modegemm<<<dim3(M, 2), 256>>>(Wr, Wi);
    k_conv<<<dim3(B, 8), 256>>>();
    k_final<<<dim3(S / 32, B), 256, SMEM_BYTES>>>(u, skw, skb, w1, b1, w2, b2, out);
}

// round 3
// speedup vs baseline: 2.9685x; 2.9685x over previous
#include <cuda_runtime.h>
#include <cuda.h>
#include <math.h>
#include <stdint.h>

#define B 8
#define S 8192
#define H 256
#define M 64
#define KC 8

// ---------------- scratch (device globals) ----------------
__device__ float2 g_ph[S];
__device__ float2 g_basis[S * M];            // [t][m] (cos,sin) for forward DFT
__device__ float  g_basis2[S * 128];         // [t][0:64]=cos, [64:128]=-sin (iDFT A)
__device__ float  g_utr[B*M*H], g_uti[B*M*H];
__device__ float  g_sr [B*M*H], g_si [B*M*H];
__device__ float  g_cvt[B*H*128];            // [b][h][0:64]=cvr*SC, [64:128]=cvi*SC
__device__ float  g_part[B*4*KC*2*4096];
__device__ float  g_act[B*S*H];              // gelu(conv+skip)
__device__ float  g_h  [B*S*128];            // gelu(mlp1)

// ---------------- helpers ----------------
__device__ __forceinline__ void fma2(float2 &d, float2 a, float2 b) {
    asm("fma.rn.f32x2 %0, %1, %2, %0;"
        : "+l"(*reinterpret_cast<unsigned long long *>(&d))
        : "l"(*reinterpret_cast<unsigned long long *>(&a)),
          "l"(*reinterpret_cast<unsigned long long *>(&b)));
}
__device__ __forceinline__ float gelu(float x) {
    return 0.5f * x * (1.0f + erff(x * 0.70710678118654752f));
}
__device__ __forceinline__ uint32_t tf32u(float x) {
    uint32_t r; asm("cvt.rna.tf32.f32 %0, %1;" : "=r"(r) : "f"(x));
    return r;
}
__device__ __forceinline__ float tf32r(float x) { return __uint_as_float(tf32u(x)); }
__device__ __forceinline__ uint32_t smem_u32(const void* p) {
    uint32_t a; asm("{ .reg .u64 t; cvta.to.shared.u64 t, %1; cvt.u32.u64 %0, t; }" : "=r"(a) : "l"(p));
    return a;
}

__device__ __forceinline__ void mma_tf32(float c[4], uint32_t a0, uint32_t a1, uint32_t a2, uint32_t a3,
                                         uint32_t b0, uint32_t b1) {
    asm volatile("mma.sync.aligned.m16n8k8.row.col.f32.tf32.tf32.f32 "
        "{%0,%1,%2,%3}, {%4,%5,%6,%7}, {%8,%9}, {%0,%1,%2,%3};"
        : "+f"(c[0]), "+f"(c[1]), "+f"(c[2]), "+f"(c[3])
        : "r"(a0), "r"(a1), "r"(a2), "r"(a3), "r"(b0), "r"(b1));
}

// ---------------- K0: phase + basis tables ----------------
__global__ void k_phase() {
    int p = blockIdx.x * 256 + threadIdx.x;
    if (p >= S) return;
    float ang = (float)p * (6.283185307179586f / 8192.0f);
    float sn, cn; sincosf(ang, &sn, &cn);
    g_ph[p] = make_float2(cn, sn);
}
__global__ void k_basis() {
    int idx = blockIdx.x * 256 + threadIdx.x;
    if (idx >= S * M) return;
    int t = idx >> 6, m = idx & 63;
    g_basis[idx] = g_ph[(t * m) & (S - 1)];
}
__global__ void k_basis2() {
    int idx = blockIdx.x * 256 + threadIdx.x;
    if (idx >= S * 128) return;
    int t = idx >> 7, m = idx & 127;
    float v;
    if (m < 64) v =  g_ph[(t * m) & (S - 1)].x;
    else        v = -g_ph[(t * (m - 64)) & (S - 1)].y;
    g_basis2[idx] = v;
}

// ---------------- K1: DFT split-K (fp32, proven) ----------------
__global__ void __launch_bounds__(256) k_dft(const float *__restrict__ u) {
    __shared__ __align__(16) float2 u2s[16][32];
    __shared__ __align__(16) float2 bss[16][64];
    int b = blockIdx.x, ht = blockIdx.y, kc = blockIdx.z;
    int tid = threadIdx.x;
    int m0  = (tid >> 4) << 2;
    int hp0 = (tid & 15) << 1;
    int h0  = ht * 64;
    float2 ar[4][2], ai[4][2];
#pragma unroll
    for (int i = 0; i < 4; i++)
#pragma unroll
        for (int j = 0; j < 2; j++) { ar[i][j] = make_float2(0.f,0.f); ai[i][j] = make_float2(0.f,0.f); }
    const float2 *u2 = (const float2 *)u;
    int tstart = kc * 1024;
    for (int tc = 0; tc < 1024; tc += 16) {
        int tbase = tstart + tc;
#pragma unroll
        for (int i = 0; i < 2; i++) {
            int lin = i * 256 + tid; int tt = lin >> 5, hp = lin & 31;
            u2s[tt][hp] = u2[(size_t)(b * S + tbase + tt) * 128 + (h0 >> 1) + hp];
        }
#pragma unroll
        for (int i = 0; i < 4; i++) {
            int lin = i * 256 + tid; int tt = lin >> 6, m = lin & 63;
            bss[tt][m] = g_basis[(tbase + tt) * 64 + m];
        }
        __syncthreads();
#pragma unroll
        for (int tt = 0; tt < 16; tt++) {
            float2 uu0 = u2s[tt][hp0], uu1 = u2s[tt][hp0 + 1];
#pragma unroll
            for (int im = 0; im < 4; im++) {
                float2 cs = bss[tt][m0 + im];
                float2 cc = make_float2(cs.x, cs.x);
                float2 ns = make_float2(-cs.y, -cs.y);
                fma2(ar[im][0], uu0, cc); fma2(ai[im][0], uu0, ns);
                fma2(ar[im][1], uu1, cc); fma2(ai[im][1], uu1, ns);
            }
        }
        __syncthreads();
    }
    float2 *pr = (float2 *)&g_part[(size_t)((b * 4 + ht) * KC + kc) * 8192];
    float2 *pi = pr + 2048;
#pragma unroll
    for (int im = 0; im < 4; im++)
#pragma unroll
        for (int j = 0; j < 2; j++) {
            pr[(m0 + im) * 32 + hp0 + j] = ar[im][j];
            pi[(m0 + im) * 32 + hp0 + j] = ai[im][j];
        }
}

__global__ void k_red() {
    int gid = blockIdx.x * 256 + threadIdx.x;
    if (gid >= B * M * H) return;
    int h = gid & 255, m = (gid >> 8) & 63, b = gid >> 14;
    int ht = h >> 6, hh = h & 63;
    float sr = 0.f, si = 0.f;
#pragma unroll
    for (int kc = 0; kc < KC; kc++) {
        const float *p = &g_part[(size_t)((b * 4 + ht) * KC + kc) * 8192 + m * 64 + hh];
        sr += p[0]; si += p[4096];
    }
    g_utr[gid] = sr; g_uti[gid] = si;
}

// ---------------- K2: per-mode complex GEMM + GELU ----------------
__global__ void __launch_bounds__(256) k_modegemm(const float *__restrict__ Wr,
                                                  const float *__restrict__ Wi) {
    __shared__ float utr_s[8][256];
    __shared__ float uti_s[8][256];
    int m = blockIdx.x, half = blockIdx.y;
    int tid = threadIdx.x;
#pragma unroll
    for (int i = 0; i < 8; i++) {
        int lin = i * 256 + tid; int bb = lin >> 8, h = lin & 255;
        utr_s[bb][h] = g_utr[(bb * 64 + m) * 256 + h];
        uti_s[bb][h] = g_uti[(bb * 64 + m) * 256 + h];
    }
    __syncthreads();
    int ho = half * 128 + (tid & 127);
    int bg = (tid >> 7) * 4;
    float accr[4] = {0,0,0,0}, acci[4] = {0,0,0,0};
    const float *wrp = Wr + (size_t)m * 65536 + ho;
    const float *wip = Wi + (size_t)m * 65536 + ho;
#pragma unroll 4
    for (int hk = 0; hk < 256; hk++) {
        float wr = wrp[(size_t)hk * 256], wi = wip[(size_t)hk * 256];
#pragma unroll
        for (int ib = 0; ib < 4; ib++) {
            float ur = utr_s[bg + ib][hk], ui = uti_s[bg + ib][hk];
            accr[ib] += ur * wr - ui * wi;
            acci[ib] += ur * wi + ui * wr;
        }
    }
#pragma unroll
    for (int ib = 0; ib < 4; ib++) {
        int o = ((bg + ib) * 64 + m) * 256 + ho;
        g_sr[o] = gelu(accr[ib]);
        g_si[o] = gelu(acci[ib]);
    }
}

// ---------------- K3: circular convolution -> g_cvt (transposed) ----------------
__global__ void __launch_bounds__(256) k_conv() {
    __shared__ __align__(16) float utr_s[64][32];
    __shared__ __align__(16) float uti_s[64][32];
    __shared__ __align__(16) float sr_s[64][32];
    __shared__ __align__(16) float si_s[64][32];
    int b = blockIdx.x, ht = blockIdx.y;
    int h0 = ht * 32;
    int tid = threadIdx.x;
#pragma unroll
    for (int i = 0; i < 8; i++) {
        int lin = i * 256 + tid; int k = lin >> 5, hh = lin & 31;
        int o = (b * 64 + k) * 256 + h0 + hh;
        utr_s[k][hh] = g_utr[o]; uti_s[k][hh] = g_uti[o];
        sr_s[k][hh]  = g_sr[o];  si_s[k][hh]  = g_si[o];
    }
    __syncthreads();
    int m0 = (tid >> 4) << 2;
    int hp = tid & 15;
    float2 cr[4], ci[4];
#pragma unroll
    for (int i = 0; i < 4; i++) { cr[i] = make_float2(0.f,0.f); ci[i] = make_float2(0.f,0.f); }
    for (int k = 0; k < 64; k++) {
        float2 ua = ((float2 *)utr_s[k])[hp];
        float2 ub = ((float2 *)uti_s[k])[hp];
#pragma unroll
        for (int im = 0; im < 4; im++) {
            int j = ((m0 + im) - k) & 63;
            float2 br = ((float2 *)sr_s[j])[hp];
            float2 bi = ((float2 *)si_s[j])[hp];
            float2 nbi = make_float2(-bi.x, -bi.y);
            fma2(cr[im], ua, br);  fma2(cr[im], ub, nbi);
            fma2(ci[im], ua, bi);  fma2(ci[im], ub, br);
        }
    }
    const float SC = 1.0f / 65536.0f;
    float *base = g_cvt + (size_t)b * 256 * 128;
    int hA = h0 + 2 * hp, hB = hA + 1;
#pragma unroll
    for (int im = 0; im < 4; im++) {
        int m = m0 + im;
        base[hA * 128 + m]      = cr[im].x * SC;
        base[hB * 128 + m]      = cr[im].y * SC;
        base[hA * 128 + 64 + m] = ci[im].x * SC;
        base[hB * 128 + 64 + m] = ci[im].y * SC;
    }
}

// ---------------- tf32 mma.sync GEMM (modes 1,2,3) ----------------
// CTA: 128 rows x 128 cols, 256 threads, warp tile 32x64 (warp grid 4x2).
// K chunked by 32, cp.async double buffer, smem row stride 36 floats.
#define ROWP 36
#define BUF_FLOATS (128 * ROWP * 2)        // As + Bs per buffer
#define GEMM_SMEM_BYTES (BUF_FLOATS * 2 * 4)

__device__ __forceinline__ void stage_tile(uint32_t sbase, const float *__restrict__ g, int stride) {
    int tid = threadIdx.x;
#pragma unroll
    for (int it = 0; it < 4; it++) {
        int v = it * 256 + tid;
        int r = v >> 3, j = v & 7;
        uint32_t sa = sbase + (uint32_t)(r * ROWP + j * 4) * 4u;
        const float *ga = g + (size_t)r * stride + j * 4;
        asm volatile("cp.async.cg.shared.global [%0], [%1], 16;" :: "r"(sa), "l"(ga) : "memory");
    }
}

template <int MODE>
__global__ void __launch_bounds__(256) k_gemm(
    const float *__restrict__ u,  const float *__restrict__ skw,
    const float *__restrict__ skb, const float *__restrict__ w1,
    const float *__restrict__ b1,  const float *__restrict__ w2,
    const float *__restrict__ b2,  float *__restrict__ out) {
    extern __shared__ __align__(16) float sm[];
    constexpr int KTOT = (MODE == 1) ? 384 : (MODE == 2) ? 256 : 128;
    constexpr int NC = KTOT / 32;

    int tid = threadIdx.x, lane = tid & 31, w = tid >> 5;
    int wm = w & 3, wn = w >> 2;           // warp grid 4 (m) x 2 (n)
    int g = lane >> 2, tig = lane & 3;
    int t0 = blockIdx.x * 128, n0 = blockIdx.y * 128, b = blockIdx.z;

    uint32_t s0 = smem_u32(sm);

    float acc[2][8][4];
#pragma unroll
    for (int mt = 0; mt < 2; mt++)
#pragma unroll
        for (int nt = 0; nt < 8; nt++)
#pragma unroll
            for (int q = 0; q < 4; q++) acc[mt][nt][q] = 0.f;

    // chunk source resolver
    auto srcs = [&](int c, const float *&sa, int &stA, const float *&sb, int &stB) {
        if (MODE == 1) {
            if (c < 4) {
                sa = g_basis2 + (size_t)t0 * 128 + c * 32;               stA = 128;
                sb = g_cvt + (size_t)b * 32768 + (size_t)n0 * 128 + c * 32; stB = 128;
            } else {
                sa = u + ((size_t)b * S + t0) * 256 + (c - 4) * 32;      stA = 256;
                sb = skw + (size_t)n0 * 256 + (c - 4) * 32;              stB = 256;
            }
        } else if (MODE == 2) {
            sa = g_act + ((size_t)b * S + t0) * 256 + c * 32;            stA = 256;
            sb = w1 + (size_t)n0 * 256 + c * 32;                         stB = 256;
        } else {
            sa = g_h + ((size_t)b * S + t0) * 128 + c * 32;              stA = 128;
            sb = w2 + (size_t)n0 * 128 + c * 32;                         stB = 128;
        }
    };

    {
        const float *sa, *sb; int stA, stB;
        srcs(0, sa, stA, sb, stB);
        stage_tile(s0, sa, stA);
        stage_tile(s0 + 128 * ROWP * 4, sb, stB);
        asm volatile("cp.async.commit_group;" ::: "memory");
    }

    for (int c = 0; c < NC; c++) {
        int buf = c & 1;
        if (c + 1 < NC) {
            const float *sa, *sb; int stA, stB;
            srcs(c + 1, sa, stA, sb, stB);
            uint32_t nb = s0 + (uint32_t)(((c + 1) & 1) * BUF_FLOATS) * 4u;
            stage_tile(nb, sa, stA);
            stage_tile(nb + 128 * ROWP * 4, sb, stB);
            asm volatile("cp.async.commit_group;" ::: "memory");
            asm volatile("cp.async.wait_group 1;" ::: "memory");
        } else {
            asm volatile("cp.async.wait_group 0;" ::: "memory");
        }
        __syncthreads();

        const float *As = sm + buf * BUF_FLOATS;
        const float *Bs = As + 128 * ROWP;
#pragma unroll
        for (int k8 = 0; k8 < 4; k8++) {
            int k0 = k8 * 8;
            uint32_t af[2][4];
#pragma unroll
            for (int mt = 0; mt < 2; mt++) {
                int r = wm * 32 + mt * 16 + g;
                af[mt][0] = tf32u(As[r * ROWP + k0 + tig]);
                af[mt][1] = tf32u(As[(r + 8) * ROWP + k0 + tig]);
                af[mt][2] = tf32u(As[r * ROWP + k0 + tig + 4]);
                af[mt][3] = tf32u(As[(r + 8) * ROWP + k0 + tig + 4]);
            }
#pragma unroll
            for (int nt = 0; nt < 8; nt++) {
                int br = wn * 64 + nt * 8 + g;
                uint32_t b0 = tf32u(Bs[br * ROWP + k0 + tig]);
                uint32_t b1 = tf32u(Bs[br * ROWP + k0 + tig + 4]);
#pragma unroll
                for (int mt = 0; mt < 2; mt++)
                    mma_tf32(acc[mt][nt], af[mt][0], af[mt][1], af[mt][2], af[mt][3], b0, b1);
            }
        }
        __syncthreads();
    }

    // ---- epilogue ----
    const float *bias = (MODE == 1) ? skb : (MODE == 2) ? b1 : b2;
    float *dst; int dstride;
    if (MODE == 1) { dst = g_act + ((size_t)b * S) * 256; dstride = 256; }
    else if (MODE == 2) { dst = g_h + ((size_t)b * S) * 128; dstride = 128; }
    else { dst = out + ((size_t)b * S) * 256; dstride = 256; }

#pragma unroll
    for (int mt = 0; mt < 2; mt++) {
#pragma unroll
        for (int nt = 0; nt < 8; nt++) {
            int row = t0 + wm * 32 + mt * 16 + g;
            int col = n0 + wn * 64 + nt * 8 + 2 * tig;
            float bz0 = __ldg(bias + col), bz1 = __ldg(bias + col + 1);
            float v0 = acc[mt][nt][0] + bz0, v1 = acc[mt][nt][1] + bz1;
            float v2 = acc[mt][nt][2] + bz0, v3 = acc[mt][nt][3] + bz1;
            if (MODE != 3) {
                v0 = tf32r(gelu(v0)); v1 = tf32r(gelu(v1));
                v2 = tf32r(gelu(v2)); v3 = tf32r(gelu(v3));
            }
            *(float2 *)(dst + (size_t)row * dstride + col) = make_float2(v0, v1);
            *(float2 *)(dst + (size_t)(row + 8) * dstride + col) = make_float2(v2, v3);
        }
    }
}

// ---------------- launch ----------------
extern "C" void kernel_launch(void *const *d_in, const int *in_sizes, int n_in,
                              void *d_out, int out_size) {
    const float *u   = (const float *)d_in[0];
    const float *Wr  = (const float *)d_in[1];
    const float *Wi  = (const float *)d_in[2];
    const float *skw = (const float *)d_in[3];
    const float *skb = (const float *)d_in[4];
    const float *w1  = (const float *)d_in[5];
    const float *b1  = (const float *)d_in[6];
    const float *w2  = (const float *)d_in[7];
    const float *b2  = (const float *)d_in[8];
    float *out = (float *)d_out;

    cudaFuncSetAttribute(k_gemm<1>, cudaFuncAttributeMaxDynamicSharedMemorySize, GEMM_SMEM_BYTES);
    cudaFuncSetAttribute(k_gemm<2>, cudaFuncAttributeMaxDynamicSharedMemorySize, GEMM_SMEM_BYTES);
    cudaFuncSetAttribute(k_gemm<3>, cudaFuncAttributeMaxDynamicSharedMemorySize, GEMM_SMEM_BYTES);

    k_phase<<<(S + 255) / 256, 256>>>();
    k_basis<<<(S * M + 255) / 256, 256>>>();
    k_basis2<<<(S * 128 + 255) / 256, 256>>>();
    k_dft<<<dim3(B, 4, KC), 256>>>(u);
    k_red<<<(B * M * H + 255) / 256, 256>>>();
    k_modegemm<<<dim3(M, 2), 256>>>(Wr, Wi);
    k_conv<<<dim3(B, 8), 256>>>();
    k_gemm<1><<<dim3(64, 2, B), 256, GEMM_SMEM_BYTES>>>(u, skw, skb, w1, b1, w2, b2, out);
    k_gemm<2><<<dim3(64, 1, B), 256, GEMM_SMEM_BYTES>>>(u, skw, skb, w1, b1, w2, b2, out);
    k_gemm<3><<<dim3(64, 2, B), 256, GEMM_SMEM_BYTES>>>(u, skw, skb, w1, b1, w2, b2, out);
}

// round 4
// speedup vs baseline: 3.2606x; 1.0984x over previous
#include <cuda_runtime.h>
#include <cuda.h>
#include <cuda_bf16.h>
#include <math.h>
#include <stdint.h>

#define B 8
#define S 8192
#define H 256
#define M 64
#define DFT_KS 16
#define DFT_CH (S / DFT_KS)   // 512

// ---------------- scratch (device globals) ----------------
__device__ float2 g_ph[S];
__device__ __nv_bfloat16 g_bfh[128 * S];     // DFT basis hi  [m'][t]
__device__ __nv_bfloat16 g_bfl[128 * S];     // DFT basis lo
__device__ float  g_basis2[S * 128];         // iDFT A: [t][0:64]=cos, [64:128]=-sin
__device__ float  g_utr[B*M*H], g_uti[B*M*H];
__device__ float  g_sr [B*M*H], g_si [B*M*H];
__device__ float  g_cvt[B*H*128];            // [b][h][0:64]=cvr*SC, [64:128]=cvi*SC
__device__ float  g_part[B * 2 * DFT_KS * 16384];   // DFT partials (16.8 MB)
__device__ float  g_mgr[64*2*4*1024], g_mgi[64*2*4*1024];  // modegemm partials
__device__ float  g_act[B*S*H];
__device__ float  g_h  [B*S*128];

// ---------------- helpers ----------------
__device__ __forceinline__ void fma2(float2 &d, float2 a, float2 b) {
    asm("fma.rn.f32x2 %0, %1, %2, %0;"
        : "+l"(*reinterpret_cast<unsigned long long *>(&d))
        : "l"(*reinterpret_cast<unsigned long long *>(&a)),
          "l"(*reinterpret_cast<unsigned long long *>(&b)));
}
__device__ __forceinline__ float gelu(float x) {
    return 0.5f * x * (1.0f + erff(x * 0.70710678118654752f));
}
__device__ __forceinline__ uint32_t tf32u(float x) {
    uint32_t r; asm("cvt.rna.tf32.f32 %0, %1;" : "=r"(r) : "f"(x));
    return r;
}
__device__ __forceinline__ float tf32r(float x) { return __uint_as_float(tf32u(x)); }
__device__ __forceinline__ uint32_t smem_u32(const void* p) {
    uint32_t a; asm("{ .reg .u64 t; cvta.to.shared.u64 t, %1; cvt.u32.u64 %0, t; }" : "=r"(a) : "l"(p));
    return a;
}
__device__ __forceinline__ void mma_tf32(float c[4], uint32_t a0, uint32_t a1, uint32_t a2, uint32_t a3,
                                         uint32_t b0, uint32_t b1) {
    asm volatile("mma.sync.aligned.m16n8k8.row.col.f32.tf32.tf32.f32 "
        "{%0,%1,%2,%3}, {%4,%5,%6,%7}, {%8,%9}, {%0,%1,%2,%3};"
        : "+f"(c[0]), "+f"(c[1]), "+f"(c[2]), "+f"(c[3])
        : "r"(a0), "r"(a1), "r"(a2), "r"(a3), "r"(b0), "r"(b1));
}
__device__ __forceinline__ void mma_bf16(float c[4], const uint32_t a[4], uint32_t b0, uint32_t b1) {
    asm volatile("mma.sync.aligned.m16n8k16.row.col.f32.bf16.bf16.f32 "
        "{%0,%1,%2,%3}, {%4,%5,%6,%7}, {%8,%9}, {%0,%1,%2,%3};"
        : "+f"(c[0]), "+f"(c[1]), "+f"(c[2]), "+f"(c[3])
        : "r"(a[0]), "r"(a[1]), "r"(a[2]), "r"(a[3]), "r"(b0), "r"(b1));
}

// ---------------- K0: tables ----------------
__global__ void k_phase() {
    int p = blockIdx.x * 256 + threadIdx.x;
    if (p >= S) return;
    float ang = (float)p * (6.283185307179586f / 8192.0f);
    float sn, cn; sincosf(ang, &sn, &cn);
    g_ph[p] = make_float2(cn, sn);
}
__global__ void k_basisF() {
    int idx = blockIdx.x * 256 + threadIdx.x;       // < 128*8192
    int mp = idx >> 13, t = idx & 8191;
    float v;
    if (mp < 64) v =  g_ph[(mp * t) & 8191].x;
    else         v = -g_ph[((mp - 64) * t) & 8191].y;
    __nv_bfloat16 hi = __float2bfloat16(v);
    g_bfh[idx] = hi;
    g_bfl[idx] = __float2bfloat16(v - __bfloat162float(hi));
}
__global__ void k_basis2() {
    int idx = blockIdx.x * 256 + threadIdx.x;
    if (idx >= S * 128) return;
    int t = idx >> 7, m = idx & 127;
    float v;
    if (m < 64) v =  g_ph[(t * m) & (S - 1)].x;
    else        v = -g_ph[(t * (m - 64)) & (S - 1)].y;
    g_basis2[idx] = v;
}

// ---------------- DFT via bf16x2 3-pass mma ----------------
// C[128 m', 128 h-tile] += basisF[128, k] @ u[k, h]^T, split-K over 16 chunks of 512.
// smem per buffer (bytes): Ahi[128][40]bf16 @0 (10240), Alo @10240, Bhi @20480, Blo @30720.
#define ABUF 10240
#define DBUF 40960
#define DFT_SMEM (2 * DBUF)

__global__ void __launch_bounds__(256) k_dftmma(const float *__restrict__ u) {
    extern __shared__ __align__(16) char sm[];
    int tid = threadIdx.x, lane = tid & 31, w = tid >> 5;
    int wm = w & 3, wn = w >> 2, g = lane >> 2, tg = lane & 3;
    int ks = blockIdx.x, nb = blockIdx.y, b = blockIdx.z;
    int tbase0 = ks * DFT_CH;
    uint32_t s0 = smem_u32(sm);

    float acc[2][8][4];
#pragma unroll
    for (int mt = 0; mt < 2; mt++)
#pragma unroll
        for (int nt = 0; nt < 8; nt++)
#pragma unroll
            for (int q = 0; q < 4; q++) acc[mt][nt][q] = 0.f;

    auto stageA = [&](int c, int buf) {
        int t0 = tbase0 + c * 32;
#pragma unroll
        for (int it = 0; it < 2; it++) {
            int idx = it * 256 + tid;              // 512 16B chunks per table
            int r = idx >> 2, seg = idx & 3;
            uint32_t sh = s0 + buf * DBUF + (uint32_t)(r * 80 + seg * 16);
            const __nv_bfloat16 *gh = g_bfh + (size_t)r * S + t0 + seg * 8;
            const __nv_bfloat16 *gl = g_bfl + (size_t)r * S + t0 + seg * 8;
            asm volatile("cp.async.cg.shared.global [%0], [%1], 16;" :: "r"(sh), "l"(gh) : "memory");
            asm volatile("cp.async.cg.shared.global [%0], [%1], 16;" :: "r"(sh + ABUF), "l"(gl) : "memory");
        }
    };
    auto stageB = [&](int c, int buf) {
        int t0 = tbase0 + c * 32;
        __nv_bfloat16 *Bh = (__nv_bfloat16 *)(sm + buf * DBUF + 2 * ABUF);
        __nv_bfloat16 *Bl = Bh + ABUF / 2;
#pragma unroll
        for (int it = 0; it < 4; it++) {
            int lin = it * 256 + tid;
            int t = lin >> 5, hq = lin & 31;
            float4 v = *(const float4 *)(u + ((size_t)b * S + t0 + t) * 256 + nb * 128 + hq * 4);
            float vv[4] = {v.x, v.y, v.z, v.w};
#pragma unroll
            for (int j = 0; j < 4; j++) {
                int h = hq * 4 + j;
                __nv_bfloat16 hi = __float2bfloat16(vv[j]);
                __nv_bfloat16 lo = __float2bfloat16(vv[j] - __bfloat162float(hi));
                Bh[h * 40 + t] = hi;
                Bl[h * 40 + t] = lo;
            }
        }
    };

    stageA(0, 0); stageB(0, 0);
    asm volatile("cp.async.commit_group;" ::: "memory");

    for (int c = 0; c < 16; c++) {
        int buf = c & 1;
        if (c < 15) {
            stageA(c + 1, buf ^ 1); stageB(c + 1, buf ^ 1);
            asm volatile("cp.async.commit_group;" ::: "memory");
            asm volatile("cp.async.wait_group 1;" ::: "memory");
        } else {
            asm volatile("cp.async.wait_group 0;" ::: "memory");
        }
        __syncthreads();

        const uint32_t *Ah32 = (const uint32_t *)(sm + buf * DBUF);
        const uint32_t *Al32 = Ah32 + 2560;
        const uint32_t *Bh32 = Ah32 + 5120;
        const uint32_t *Bl32 = Ah32 + 7680;
#pragma unroll
        for (int kh = 0; kh < 2; kh++) {
            int ko = kh * 8;
            uint32_t ah[2][4], al[2][4];
#pragma unroll
            for (int mt = 0; mt < 2; mt++) {
                int r = wm * 32 + mt * 16 + g;
                ah[mt][0] = Ah32[r * 20 + ko + tg];
                ah[mt][1] = Ah32[(r + 8) * 20 + ko + tg];
                ah[mt][2] = Ah32[r * 20 + ko + 4 + tg];
                ah[mt][3] = Ah32[(r + 8) * 20 + ko + 4 + tg];
                al[mt][0] = Al32[r * 20 + ko + tg];
                al[mt][1] = Al32[(r + 8) * 20 + ko + tg];
                al[mt][2] = Al32[r * 20 + ko + 4 + tg];
                al[mt][3] = Al32[(r + 8) * 20 + ko + 4 + tg];
            }
#pragma unroll
            for (int nt = 0; nt < 8; nt++) {
                int n = wn * 64 + nt * 8 + g;
                uint32_t bh0 = Bh32[n * 20 + ko + tg], bh1 = Bh32[n * 20 + ko + 4 + tg];
                uint32_t bl0 = Bl32[n * 20 + ko + tg], bl1 = Bl32[n * 20 + ko + 4 + tg];
#pragma unroll
                for (int mt = 0; mt < 2; mt++) {
                    mma_bf16(acc[mt][nt], ah[mt], bh0, bh1);
                    mma_bf16(acc[mt][nt], ah[mt], bl0, bl1);
                    mma_bf16(acc[mt][nt], al[mt], bh0, bh1);
                }
            }
        }
        __syncthreads();
    }

    float *pp = g_part + (size_t)((b * 2 + nb) * DFT_KS + ks) * 16384;
#pragma unroll
    for (int mt = 0; mt < 2; mt++)
#pragma unroll
        for (int nt = 0; nt < 8; nt++) {
            int row = wm * 32 + mt * 16 + g;
            int col = wn * 64 + nt * 8 + 2 * tg;
            *(float2 *)(pp + row * 128 + col)       = make_float2(acc[mt][nt][0], acc[mt][nt][1]);
            *(float2 *)(pp + (row + 8) * 128 + col) = make_float2(acc[mt][nt][2], acc[mt][nt][3]);
        }
}

__global__ void k_dftred() {
    int gid = blockIdx.x * 256 + threadIdx.x;       // < B*128*256
    int h = gid & 255, row = (gid >> 8) & 127, b = gid >> 15;
    int nb = h >> 7, cl = h & 127;
    const float *p = g_part + (size_t)((b * 2 + nb) * DFT_KS) * 16384 + row * 128 + cl;
    float s = 0.f;
#pragma unroll
    for (int ks = 0; ks < DFT_KS; ks++) s += p[(size_t)ks * 16384];
    if (row < 64) g_utr[(b * 64 + row) * 256 + h] = s;
    else          g_uti[(b * 64 + row - 64) * 256 + h] = s;
}

// ---------------- K2: per-mode complex GEMM (split-K x4) + reduce/GELU ----------------
__global__ void __launch_bounds__(256) k_modegemm(const float *__restrict__ Wr,
                                                  const float *__restrict__ Wi) {
    __shared__ float utr_s[8][256];
    __shared__ float uti_s[8][256];
    int m = blockIdx.x, half = blockIdx.y, kk = blockIdx.z;
    int tid = threadIdx.x;
#pragma unroll
    for (int i = 0; i < 8; i++) {
        int lin = i * 256 + tid; int bb = lin >> 8, h = lin & 255;
        utr_s[bb][h] = g_utr[(bb * 64 + m) * 256 + h];
        uti_s[bb][h] = g_uti[(bb * 64 + m) * 256 + h];
    }
    __syncthreads();
    int ho = half * 128 + (tid & 127);
    int bg = (tid >> 7) * 4;
    float accr[4] = {0,0,0,0}, acci[4] = {0,0,0,0};
    const float *wrp = Wr + (size_t)m * 65536 + ho;
    const float *wip = Wi + (size_t)m * 65536 + ho;
    int hk0 = kk * 64;
#pragma unroll 4
    for (int hk = hk0; hk < hk0 + 64; hk++) {
        float wr = wrp[(size_t)hk * 256], wi = wip[(size_t)hk * 256];
#pragma unroll
        for (int ib = 0; ib < 4; ib++) {
            float ur = utr_s[bg + ib][hk], ui = uti_s[bg + ib][hk];
            accr[ib] += ur * wr - ui * wi;
            acci[ib] += ur * wi + ui * wr;
        }
    }
    float *pr = g_mgr + (size_t)(((m * 2 + half) * 4) + kk) * 1024;
    float *pi = g_mgi + (size_t)(((m * 2 + half) * 4) + kk) * 1024;
#pragma unroll
    for (int ib = 0; ib < 4; ib++) {
        pr[(bg + ib) * 128 + (tid & 127)] = accr[ib];
        pi[(bg + ib) * 128 + (tid & 127)] = acci[ib];
    }
}

__global__ void k_mgred() {
    int gid = blockIdx.x * 256 + threadIdx.x;       // < B*M*H = 131072
    int h = gid & 255, m = (gid >> 8) & 63, b = gid >> 14;
    int half = h >> 7, ho = h & 127;
    size_t base = (size_t)((m * 2 + half) * 4) * 1024 + b * 128 + ho;
    float sr = 0.f, si = 0.f;
#pragma unroll
    for (int kk = 0; kk < 4; kk++) { sr += g_mgr[base + kk * 1024]; si += g_mgi[base + kk * 1024]; }
    g_sr[gid] = gelu(sr);
    g_si[gid] = gelu(si);
}

// ---------------- K3: circular convolution -> g_cvt (transposed) ----------------
__global__ void __launch_bounds__(256) k_conv() {
    __shared__ __align__(16) float utr_s[64][32];
    __shared__ __align__(16) float uti_s[64][32];
    __shared__ __align__(16) float sr_s[64][32];
    __shared__ __align__(16) float si_s[64][32];
    int b = blockIdx.x, ht = blockIdx.y;
    int h0 = ht * 32;
    int tid = threadIdx.x;
#pragma unroll
    for (int i = 0; i < 8; i++) {
        int lin = i * 256 + tid; int k = lin >> 5, hh = lin & 31;
        int o = (b * 64 + k) * 256 + h0 + hh;
        utr_s[k][hh] = g_utr[o]; uti_s[k][hh] = g_uti[o];
        sr_s[k][hh]  = g_sr[o];  si_s[k][hh]  = g_si[o];
    }
    __syncthreads();
    int m0 = (tid >> 4) << 2;
    int hp = tid & 15;
    float2 cr[4], ci[4];
#pragma unroll
    for (int i = 0; i < 4; i++) { cr[i] = make_float2(0.f,0.f); ci[i] = make_float2(0.f,0.f); }
    for (int k = 0; k < 64; k++) {
        float2 ua = ((float2 *)utr_s[k])[hp];
        float2 ub = ((float2 *)uti_s[k])[hp];
#pragma unroll
        for (int im = 0; im < 4; im++) {
            int j = ((m0 + im) - k) & 63;
            float2 br = ((float2 *)sr_s[j])[hp];
            float2 bi = ((float2 *)si_s[j])[hp];
            float2 nbi = make_float2(-bi.x, -bi.y);
            fma2(cr[im], ua, br);  fma2(cr[im], ub, nbi);
            fma2(ci[im], ua, bi);  fma2(ci[im], ub, br);
        }
    }
    const float SC = 1.0f / 65536.0f;
    float *base = g_cvt + (size_t)b * 256 * 128;
    int hA = h0 + 2 * hp, hB = hA + 1;
#pragma unroll
    for (int im = 0; im < 4; im++) {
        int m = m0 + im;
        base[hA * 128 + m]      = cr[im].x * SC;
        base[hB * 128 + m]      = cr[im].y * SC;
        base[hA * 128 + 64 + m] = ci[im].x * SC;
        base[hB * 128 + 64 + m] = ci[im].y * SC;
    }
}

// ---------------- tf32 mma.sync GEMM (modes 1,2,3) ----------------
#define ROWP 36
#define BUF_FLOATS (128 * ROWP * 2)
#define GEMM_SMEM_BYTES (BUF_FLOATS * 2 * 4)

__device__ __forceinline__ void stage_tile(uint32_t sbase, const float *__restrict__ g, int stride) {
    int tid = threadIdx.x;
#pragma unroll
    for (int it = 0; it < 4; it++) {
        int v = it * 256 + tid;
        int r = v >> 3, j = v & 7;
        uint32_t sa = sbase + (uint32_t)(r * ROWP + j * 4) * 4u;
        const float *ga = g + (size_t)r * stride + j * 4;
        asm volatile("cp.async.cg.shared.global [%0], [%1], 16;" :: "r"(sa), "l"(ga) : "memory");
    }
}

template <int MODE>
__global__ void __launch_bounds__(256) k_gemm(
    const float *__restrict__ u,  const float *__restrict__ skw,
    const float *__restrict__ skb, const float *__restrict__ w1,
    const float *__restrict__ b1,  const float *__restrict__ w2,
    const float *__restrict__ b2,  float *__restrict__ out) {
    extern __shared__ __align__(16) float smf[];
    constexpr int KTOT = (MODE == 1) ? 384 : (MODE == 2) ? 256 : 128;
    constexpr int NC = KTOT / 32;

    int tid = threadIdx.x, lane = tid & 31, w = tid >> 5;
    int wm = w & 3, wn = w >> 2;
    int g = lane >> 2, tig = lane & 3;
    int t0 = blockIdx.x * 128, n0 = blockIdx.y * 128, b = blockIdx.z;

    uint32_t s0 = smem_u32(smf);

    float acc[2][8][4];
#pragma unroll
    for (int mt = 0; mt < 2; mt++)
#pragma unroll
        for (int nt = 0; nt < 8; nt++)
#pragma unroll
            for (int q = 0; q < 4; q++) acc[mt][nt][q] = 0.f;

    auto srcs = [&](int c, const float *&sa, int &stA, const float *&sb, int &stB) {
        if (MODE == 1) {
            if (c < 4) {
                sa = g_basis2 + (size_t)t0 * 128 + c * 32;               stA = 128;
                sb = g_cvt + (size_t)b * 32768 + (size_t)n0 * 128 + c * 32; stB = 128;
            } else {
                sa = u + ((size_t)b * S + t0) * 256 + (c - 4) * 32;      stA = 256;
                sb = skw + (size_t)n0 * 256 + (c - 4) * 32;              stB = 256;
            }
        } else if (MODE == 2) {
            sa = g_act + ((size_t)b * S + t0) * 256 + c * 32;            stA = 256;
            sb = w1 + (size_t)n0 * 256 + c * 32;                         stB = 256;
        } else {
            sa = g_h + ((size_t)b * S + t0) * 128 + c * 32;              stA = 128;
            sb = w2 + (size_t)n0 * 128 + c * 32;                         stB = 128;
        }
    };

    {
        const float *sa, *sb; int stA, stB;
        srcs(0, sa, stA, sb, stB);
        stage_tile(s0, sa, stA);
        stage_tile(s0 + 128 * ROWP * 4, sb, stB);
        asm volatile("cp.async.commit_group;" ::: "memory");
    }

    for (int c = 0; c < NC; c++) {
        int buf = c & 1;
        if (c + 1 < NC) {
            const float *sa, *sb; int stA, stB;
            srcs(c + 1, sa, stA, sb, stB);
            uint32_t nb = s0 + (uint32_t)(((c + 1) & 1) * BUF_FLOATS) * 4u;
            stage_tile(nb, sa, stA);
            stage_tile(nb + 128 * ROWP * 4, sb, stB);
            asm volatile("cp.async.commit_group;" ::: "memory");
            asm volatile("cp.async.wait_group 1;" ::: "memory");
        } else {
            asm volatile("cp.async.wait_group 0;" ::: "memory");
        }
        __syncthreads();

        const float *As = smf + buf * BUF_FLOATS;
        const float *Bs = As + 128 * ROWP;
#pragma unroll
        for (int k8 = 0; k8 < 4; k8++) {
            int k0 = k8 * 8;
            uint32_t af[2][4];
#pragma unroll
            for (int mt = 0; mt < 2; mt++) {
                int r = wm * 32 + mt * 16 + g;
                af[mt][0] = tf32u(As[r * ROWP + k0 + tig]);
                af[mt][1] = tf32u(As[(r + 8) * ROWP + k0 + tig]);
                af[mt][2] = tf32u(As[r * ROWP + k0 + tig + 4]);
                af[mt][3] = tf32u(As[(r + 8) * ROWP + k0 + tig + 4]);
            }
#pragma unroll
            for (int nt = 0; nt < 8; nt++) {
                int br = wn * 64 + nt * 8 + g;
                uint32_t b0 = tf32u(Bs[br * ROWP + k0 + tig]);
                uint32_t b1 = tf32u(Bs[br * ROWP + k0 + tig + 4]);
#pragma unroll
                for (int mt = 0; mt < 2; mt++)
                    mma_tf32(acc[mt][nt], af[mt][0], af[mt][1], af[mt][2], af[mt][3], b0, b1);
            }
        }
        __syncthreads();
    }

    const float *bias = (MODE == 1) ? skb : (MODE == 2) ? b1 : b2;
    float *dst; int dstride;
    if (MODE == 1) { dst = g_act + ((size_t)b * S) * 256; dstride = 256; }
    else if (MODE == 2) { dst = g_h + ((size_t)b * S) * 128; dstride = 128; }
    else { dst = out + ((size_t)b * S) * 256; dstride = 256; }

#pragma unroll
    for (int mt = 0; mt < 2; mt++) {
#pragma unroll
        for (int nt = 0; nt < 8; nt++) {
            int row = t0 + wm * 32 + mt * 16 + g;
            int col = n0 + wn * 64 + nt * 8 + 2 * tig;
            float bz0 = __ldg(bias + col), bz1 = __ldg(bias + col + 1);
            float v0 = acc[mt][nt][0] + bz0, v1 = acc[mt][nt][1] + bz1;
            float v2 = acc[mt][nt][2] + bz0, v3 = acc[mt][nt][3] + bz1;
            if (MODE != 3) {
                v0 = tf32r(gelu(v0)); v1 = tf32r(gelu(v1));
                v2 = tf32r(gelu(v2)); v3 = tf32r(gelu(v3));
            }
            *(float2 *)(dst + (size_t)row * dstride + col) = make_float2(v0, v1);
            *(float2 *)(dst + (size_t)(row + 8) * dstride + col) = make_float2(v2, v3);
        }
    }
}

// ---------------- launch ----------------
extern "C" void kernel_launch(void *const *d_in, const int *in_sizes, int n_in,
                              void *d_out, int out_size) {
    const float *u   = (const float *)d_in[0];
    const float *Wr  = (const float *)d_in[1];
    const float *Wi  = (const float *)d_in[2];
    const float *skw = (const float *)d_in[3];
    const float *skb = (const float *)d_in[4];
    const float *w1  = (const float *)d_in[5];
    const float *b1  = (const float *)d_in[6];
    const float *w2  = (const float *)d_in[7];
    const float *b2  = (const float *)d_in[8];
    float *out = (float *)d_out;

    cudaFuncSetAttribute(k_dftmma, cudaFuncAttributeMaxDynamicSharedMemorySize, DFT_SMEM);
    cudaFuncSetAttribute(k_gemm<1>, cudaFuncAttributeMaxDynamicSharedMemorySize, GEMM_SMEM_BYTES);
    cudaFuncSetAttribute(k_gemm<2>, cudaFuncAttributeMaxDynamicSharedMemorySize, GEMM_SMEM_BYTES);
    cudaFuncSetAttribute(k_gemm<3>, cudaFuncAttributeMaxDynamicSharedMemorySize, GEMM_SMEM_BYTES);

    k_phase<<<(S + 255) / 256, 256>>>();
    k_basisF<<<(128 * S) / 256, 256>>>();
    k_basis2<<<(S * 128 + 255) / 256, 256>>>();
    k_dftmma<<<dim3(DFT_KS, 2, B), 256, DFT_SMEM>>>(u);
    k_dftred<<<(B * 128 * 256) / 256, 256>>>();
    k_modegemm<<<dim3(M, 2, 4), 256>>>(Wr, Wi);
    k_mgred<<<(B * M * H) / 256, 256>>>();
    k_conv<<<dim3(B, 8), 256>>>();
    k_gemm<1><<<dim3(64, 2, B), 256, GEMM_SMEM_BYTES>>>(u, skw, skb, w1, b1, w2, b2, out);
    k_gemm<2><<<dim3(64, 1, B), 256, GEMM_SMEM_BYTES>>>(u, skw, skb, w1, b1, w2, b2, out);
    k_gemm<3><<<dim3(64, 2, B), 256, GEMM_SMEM_BYTES>>>(u, skw, skb, w1, b1, w2, b2, out);
}

// round 5
// speedup vs baseline: 3.8390x; 1.1774x over previous
#include <cuda_runtime.h>
#include <cuda.h>
#include <cuda_bf16.h>
#include <math.h>
#include <stdint.h>

#define B 8
#define S 8192
#define H 256
#define M 64
#define DFT_KS 16
#define DFT_CH (S / DFT_KS)   // 512

// ---------------- scratch (device globals) ----------------
__device__ float2 g_ph[S];
__device__ __nv_bfloat16 g_bfh[128 * S];     // DFT basis hi  [m'][t]
__device__ __nv_bfloat16 g_bfl[128 * S];     // DFT basis lo
__device__ __nv_bfloat16 g_ubh[B * S * H];   // u hi  [b][t][h]
__device__ __nv_bfloat16 g_ubl[B * S * H];   // u lo
__device__ float  g_basis2[S * 128];         // iDFT A: [t][0:64]=cos, [64:128]=-sin
__device__ float  g_utr[B*M*H], g_uti[B*M*H];
__device__ float  g_sr [B*M*H], g_si [B*M*H];
__device__ float  g_cvt[B*H*128];
__device__ float  g_part[B * 2 * DFT_KS * 16384];
__device__ float  g_mgr[64*2*4*1024], g_mgi[64*2*4*1024];
__device__ float  g_act[B*S*H];
__device__ float  g_h[4];                    // dead-branch symbol only

// ---------------- helpers ----------------
__device__ __forceinline__ void fma2(float2 &d, float2 a, float2 b) {
    asm("fma.rn.f32x2 %0, %1, %2, %0;"
        : "+l"(*reinterpret_cast<unsigned long long *>(&d))
        : "l"(*reinterpret_cast<unsigned long long *>(&a)),
          "l"(*reinterpret_cast<unsigned long long *>(&b)));
}
__device__ __forceinline__ float gelu(float x) {
    return 0.5f * x * (1.0f + erff(x * 0.70710678118654752f));
}
__device__ __forceinline__ uint32_t tf32u(float x) {
    uint32_t r; asm("cvt.rna.tf32.f32 %0, %1;" : "=r"(r) : "f"(x));
    return r;
}
__device__ __forceinline__ float tf32r(float x) { return __uint_as_float(tf32u(x)); }
__device__ __forceinline__ uint32_t smem_u32(const void* p) {
    uint32_t a; asm("{ .reg .u64 t; cvta.to.shared.u64 t, %1; cvt.u32.u64 %0, t; }" : "=r"(a) : "l"(p));
    return a;
}
__device__ __forceinline__ void mma_tf32(float c[4], uint32_t a0, uint32_t a1, uint32_t a2, uint32_t a3,
                                         uint32_t b0, uint32_t b1) {
    asm volatile("mma.sync.aligned.m16n8k8.row.col.f32.tf32.tf32.f32 "
        "{%0,%1,%2,%3}, {%4,%5,%6,%7}, {%8,%9}, {%0,%1,%2,%3};"
        : "+f"(c[0]), "+f"(c[1]), "+f"(c[2]), "+f"(c[3])
        : "r"(a0), "r"(a1), "r"(a2), "r"(a3), "r"(b0), "r"(b1));
}
__device__ __forceinline__ void mma_bf16(float c[4], const uint32_t a[4], uint32_t b0, uint32_t b1) {
    asm volatile("mma.sync.aligned.m16n8k16.row.col.f32.bf16.bf16.f32 "
        "{%0,%1,%2,%3}, {%4,%5,%6,%7}, {%8,%9}, {%0,%1,%2,%3};"
        : "+f"(c[0]), "+f"(c[1]), "+f"(c[2]), "+f"(c[3])
        : "r"(a[0]), "r"(a[1]), "r"(a[2]), "r"(a[3]), "r"(b0), "r"(b1));
}
#define LDSM_X4(r, addr) \
    asm volatile("ldmatrix.sync.aligned.m8n8.x4.shared.b16 {%0,%1,%2,%3}, [%4];" \
        : "=r"((r)[0]), "=r"((r)[1]), "=r"((r)[2]), "=r"((r)[3]) : "r"(addr))
#define LDSM_X4_T(r, addr) \
    asm volatile("ldmatrix.sync.aligned.m8n8.x4.trans.shared.b16 {%0,%1,%2,%3}, [%4];" \
        : "=r"((r)[0]), "=r"((r)[1]), "=r"((r)[2]), "=r"((r)[3]) : "r"(addr))
#define CPA16(dst, src) \
    asm volatile("cp.async.cg.shared.global [%0], [%1], 16;" :: "r"(dst), "l"(src) : "memory")

// ---------------- K0: tables ----------------
__global__ void k_phase() {
    int p = blockIdx.x * 256 + threadIdx.x;
    if (p >= S) return;
    float ang = (float)p * (6.283185307179586f / 8192.0f);
    float sn, cn; sincosf(ang, &sn, &cn);
    g_ph[p] = make_float2(cn, sn);
}
__global__ void k_basisF() {
    int idx = blockIdx.x * 256 + threadIdx.x;
    int mp = idx >> 13, t = idx & 8191;
    float v;
    if (mp < 64) v =  g_ph[(mp * t) & 8191].x;
    else         v = -g_ph[((mp - 64) * t) & 8191].y;
    __nv_bfloat16 hi = __float2bfloat16(v);
    g_bfh[idx] = hi;
    g_bfl[idx] = __float2bfloat16(v - __bfloat162float(hi));
}
__global__ void k_basis2() {
    int idx = blockIdx.x * 256 + threadIdx.x;
    if (idx >= S * 128) return;
    int t = idx >> 7, m = idx & 127;
    float v;
    if (m < 64) v =  g_ph[(t * m) & (S - 1)].x;
    else        v = -g_ph[(t * (m - 64)) & (S - 1)].y;
    g_basis2[idx] = v;
}

// ---------------- u -> bf16 hi/lo (coalesced, no transpose) ----------------
__global__ void k_usplit(const float *__restrict__ u) {
    size_t gid = (size_t)blockIdx.x * 256 + threadIdx.x;   // < B*S*256/4
    float4 v = ((const float4 *)u)[gid];
    float vv[4] = {v.x, v.y, v.z, v.w};
    uint32_t hh[2] = {0, 0}, ll[2] = {0, 0};
#pragma unroll
    for (int j = 0; j < 4; j++) {
        __nv_bfloat16 hi = __float2bfloat16(vv[j]);
        __nv_bfloat16 lo = __float2bfloat16(vv[j] - __bfloat162float(hi));
        hh[j >> 1] |= (uint32_t)__bfloat16_as_ushort(hi) << ((j & 1) * 16);
        ll[j >> 1] |= (uint32_t)__bfloat16_as_ushort(lo) << ((j & 1) * 16);
    }
    ((uint2 *)g_ubh)[gid] = make_uint2(hh[0], hh[1]);
    ((uint2 *)g_ubl)[gid] = make_uint2(ll[0], ll[1]);
}

// ---------------- DFT via bf16x2 3-pass mma + ldmatrix ----------------
// smem/buffer: Ah 128x40h @0 (10240B), Al @10240, Bh 32x136h @20480 (8704B), Bl @29184.
#define DBUF 37888
#define DFT_SMEM (2 * DBUF)

__global__ void __launch_bounds__(256, 2) k_dftmma() {
    extern __shared__ __align__(16) char sm[];
    int tid = threadIdx.x, lane = tid & 31, w = tid >> 5;
    int wm = w & 3, wn = w >> 2, g = lane >> 2, tg = lane & 3;
    int ks = blockIdx.x, nb = blockIdx.y, b = blockIdx.z;
    int tbase0 = ks * DFT_CH;
    uint32_t s0 = smem_u32(sm);

    float acc[2][8][4];
#pragma unroll
    for (int mt = 0; mt < 2; mt++)
#pragma unroll
        for (int nt = 0; nt < 8; nt++)
#pragma unroll
            for (int q = 0; q < 4; q++) acc[mt][nt][q] = 0.f;

    auto stage = [&](int c, int buf) {
        int t0 = tbase0 + c * 32;
        uint32_t base = s0 + buf * DBUF;
        // A: 128 rows x 4 segs of 16B, hi + lo
#pragma unroll
        for (int it = 0; it < 2; it++) {
            int idx = it * 256 + tid;
            int r = idx >> 2, seg = idx & 3;
            uint32_t sh = base + (uint32_t)(r * 80 + seg * 16);
            const __nv_bfloat16 *gh = g_bfh + (size_t)r * S + t0 + seg * 8;
            const __nv_bfloat16 *gl = g_bfl + (size_t)r * S + t0 + seg * 8;
            CPA16(sh, gh);
            CPA16(sh + 10240, gl);
        }
        // B: 32 t-rows x 16 segs of 16B (128 h), hi + lo
#pragma unroll
        for (int it = 0; it < 2; it++) {
            int idx = it * 256 + tid;
            int r = idx >> 4, seg = idx & 15;
            uint32_t sh = base + 20480 + (uint32_t)(r * 272 + seg * 16);
            const __nv_bfloat16 *gh = g_ubh + ((size_t)(b * S + t0 + r)) * 256 + nb * 128 + seg * 8;
            const __nv_bfloat16 *gl = g_ubl + ((size_t)(b * S + t0 + r)) * 256 + nb * 128 + seg * 8;
            CPA16(sh, gh);
            CPA16(sh + 8704, gl);
        }
    };

    stage(0, 0);
    asm volatile("cp.async.commit_group;" ::: "memory");

    for (int c = 0; c < 16; c++) {
        int buf = c & 1;
        if (c < 15) {
            stage(c + 1, buf ^ 1);
            asm volatile("cp.async.commit_group;" ::: "memory");
            asm volatile("cp.async.wait_group 1;" ::: "memory");
        } else {
            asm volatile("cp.async.wait_group 0;" ::: "memory");
        }
        __syncthreads();

        uint32_t base = s0 + buf * DBUF;
#pragma unroll
        for (int kh = 0; kh < 2; kh++) {
            uint32_t ah[2][4], al[2][4];
#pragma unroll
            for (int mt = 0; mt < 2; mt++) {
                uint32_t ra = base + (uint32_t)((wm * 32 + mt * 16 + (lane & 15)) * 80 + kh * 32 + (lane >> 4) * 16);
                LDSM_X4(ah[mt], ra);
                LDSM_X4(al[mt], ra + 10240);
            }
#pragma unroll
            for (int ntp = 0; ntp < 4; ntp++) {
                uint32_t rb = base + 20480 +
                    (uint32_t)((kh * 16 + (lane & 7) + ((lane >> 3) & 1) * 8) * 272 +
                               (wn * 64 + ntp * 16 + (lane >> 4) * 8) * 2);
                uint32_t bh[4], bl[4];
                LDSM_X4_T(bh, rb);
                LDSM_X4_T(bl, rb + 8704);
#pragma unroll
                for (int mt = 0; mt < 2; mt++) {
                    mma_bf16(acc[mt][2 * ntp],     ah[mt], bh[0], bh[1]);
                    mma_bf16(acc[mt][2 * ntp],     ah[mt], bl[0], bl[1]);
                    mma_bf16(acc[mt][2 * ntp],     al[mt], bh[0], bh[1]);
                    mma_bf16(acc[mt][2 * ntp + 1], ah[mt], bh[2], bh[3]);
                    mma_bf16(acc[mt][2 * ntp + 1], ah[mt], bl[2], bl[3]);
                    mma_bf16(acc[mt][2 * ntp + 1], al[mt], bh[2], bh[3]);
                }
            }
        }
        __syncthreads();
    }

    float *pp = g_part + (size_t)((b * 2 + nb) * DFT_KS + ks) * 16384;
#pragma unroll
    for (int mt = 0; mt < 2; mt++)
#pragma unroll
        for (int nt = 0; nt < 8; nt++) {
            int row = wm * 32 + mt * 16 + g;
            int col = wn * 64 + nt * 8 + 2 * tg;
            *(float2 *)(pp + row * 128 + col)       = make_float2(acc[mt][nt][0], acc[mt][nt][1]);
            *(float2 *)(pp + (row + 8) * 128 + col) = make_float2(acc[mt][nt][2], acc[mt][nt][3]);
        }
}

__global__ void k_dftred() {
    int gid = blockIdx.x * 256 + threadIdx.x;
    int h = gid & 255, row = (gid >> 8) & 127, b = gid >> 15;
    int nb = h >> 7, cl = h & 127;
    const float *p = g_part + (size_t)((b * 2 + nb) * DFT_KS) * 16384 + row * 128 + cl;
    float s = 0.f;
#pragma unroll
    for (int ks = 0; ks < DFT_KS; ks++) s += p[(size_t)ks * 16384];
    if (row < 64) g_utr[(b * 64 + row) * 256 + h] = s;
    else          g_uti[(b * 64 + row - 64) * 256 + h] = s;
}

// ---------------- K2: per-mode complex GEMM (split-K x4) + reduce/GELU ----------------
__global__ void __launch_bounds__(256) k_modegemm(const float *__restrict__ Wr,
                                                  const float *__restrict__ Wi) {
    __shared__ float utr_s[8][256];
    __shared__ float uti_s[8][256];
    int m = blockIdx.x, half = blockIdx.y, kk = blockIdx.z;
    int tid = threadIdx.x;
#pragma unroll
    for (int i = 0; i < 8; i++) {
        int lin = i * 256 + tid; int bb = lin >> 8, h = lin & 255;
        utr_s[bb][h] = g_utr[(bb * 64 + m) * 256 + h];
        uti_s[bb][h] = g_uti[(bb * 64 + m) * 256 + h];
    }
    __syncthreads();
    int ho = half * 128 + (tid & 127);
    int bg = (tid >> 7) * 4;
    float accr[4] = {0,0,0,0}, acci[4] = {0,0,0,0};
    const float *wrp = Wr + (size_t)m * 65536 + ho;
    const float *wip = Wi + (size_t)m * 65536 + ho;
    int hk0 = kk * 64;
#pragma unroll 4
    for (int hk = hk0; hk < hk0 + 64; hk++) {
        float wr = wrp[(size_t)hk * 256], wi = wip[(size_t)hk * 256];
#pragma unroll
        for (int ib = 0; ib < 4; ib++) {
            float ur = utr_s[bg + ib][hk], ui = uti_s[bg + ib][hk];
            accr[ib] += ur * wr - ui * wi;
            acci[ib] += ur * wi + ui * wr;
        }
    }
    float *pr = g_mgr + (size_t)(((m * 2 + half) * 4) + kk) * 1024;
    float *pi = g_mgi + (size_t)(((m * 2 + half) * 4) + kk) * 1024;
#pragma unroll
    for (int ib = 0; ib < 4; ib++) {
        pr[(bg + ib) * 128 + (tid & 127)] = accr[ib];
        pi[(bg + ib) * 128 + (tid & 127)] = acci[ib];
    }
}

__global__ void k_mgred() {
    int gid = blockIdx.x * 256 + threadIdx.x;
    int h = gid & 255, m = (gid >> 8) & 63, b = gid >> 14;
    int half = h >> 7, ho = h & 127;
    size_t base = (size_t)((m * 2 + half) * 4) * 1024 + b * 128 + ho;
    float sr = 0.f, si = 0.f;
#pragma unroll
    for (int kk = 0; kk < 4; kk++) { sr += g_mgr[base + kk * 1024]; si += g_mgi[base + kk * 1024]; }
    g_sr[gid] = gelu(sr);
    g_si[gid] = gelu(si);
}

// ---------------- K3: circular convolution -> g_cvt (transposed) ----------------
__global__ void __launch_bounds__(256) k_conv() {
    __shared__ __align__(16) float utr_s[64][32];
    __shared__ __align__(16) float uti_s[64][32];
    __shared__ __align__(16) float sr_s[64][32];
    __shared__ __align__(16) float si_s[64][32];
    int b = blockIdx.x, ht = blockIdx.y;
    int h0 = ht * 32;
    int tid = threadIdx.x;
#pragma unroll
    for (int i = 0; i < 8; i++) {
        int lin = i * 256 + tid; int k = lin >> 5, hh = lin & 31;
        int o = (b * 64 + k) * 256 + h0 + hh;
        utr_s[k][hh] = g_utr[o]; uti_s[k][hh] = g_uti[o];
        sr_s[k][hh]  = g_sr[o];  si_s[k][hh]  = g_si[o];
    }
    __syncthreads();
    int m0 = (tid >> 4) << 2;
    int hp = tid & 15;
    float2 cr[4], ci[4];
#pragma unroll
    for (int i = 0; i < 4; i++) { cr[i] = make_float2(0.f,0.f); ci[i] = make_float2(0.f,0.f); }
    for (int k = 0; k < 64; k++) {
        float2 ua = ((float2 *)utr_s[k])[hp];
        float2 ub = ((float2 *)uti_s[k])[hp];
#pragma unroll
        for (int im = 0; im < 4; im++) {
            int j = ((m0 + im) - k) & 63;
            float2 br = ((float2 *)sr_s[j])[hp];
            float2 bi = ((float2 *)si_s[j])[hp];
            float2 nbi = make_float2(-bi.x, -bi.y);
            fma2(cr[im], ua, br);  fma2(cr[im], ub, nbi);
            fma2(ci[im], ua, bi);  fma2(ci[im], ub, br);
        }
    }
    const float SC = 1.0f / 65536.0f;
    float *base = g_cvt + (size_t)b * 256 * 128;
    int hA = h0 + 2 * hp, hB = hA + 1;
#pragma unroll
    for (int im = 0; im < 4; im++) {
        int m = m0 + im;
        base[hA * 128 + m]      = cr[im].x * SC;
        base[hB * 128 + m]      = cr[im].y * SC;
        base[hA * 128 + 64 + m] = ci[im].x * SC;
        base[hB * 128 + 64 + m] = ci[im].y * SC;
    }
}

// ---------------- G1: tf32 mma.sync GEMM (iDFT+skip fused) ----------------
#define ROWP 36
#define BUF_FLOATS (128 * ROWP * 2)
#define GEMM_SMEM_BYTES (BUF_FLOATS * 2 * 4)

__device__ __forceinline__ void stage_tile(uint32_t sbase, const float *__restrict__ g, int stride) {
    int tid = threadIdx.x;
#pragma unroll
    for (int it = 0; it < 4; it++) {
        int v = it * 256 + tid;
        int r = v >> 3, j = v & 7;
        uint32_t sa = sbase + (uint32_t)(r * ROWP + j * 4) * 4u;
        const float *ga = g + (size_t)r * stride + j * 4;
        CPA16(sa, ga);
    }
}

template <int MODE>
__global__ void __launch_bounds__(256) k_gemm(
    const float *__restrict__ u,  const float *__restrict__ skw,
    const float *__restrict__ skb, const float *__restrict__ w1,
    const float *__restrict__ b1,  const float *__restrict__ w2,
    const float *__restrict__ b2,  float *__restrict__ out) {
    extern __shared__ __align__(16) float smf[];
    constexpr int KTOT = (MODE == 1) ? 384 : (MODE == 2) ? 256 : 128;
    constexpr int NC = KTOT / 32;

    int tid = threadIdx.x, lane = tid & 31, w = tid >> 5;
    int wm = w & 3, wn = w >> 2;
    int g = lane >> 2, tig = lane & 3;
    int t0 = blockIdx.x * 128, n0 = blockIdx.y * 128, b = blockIdx.z;

    uint32_t s0 = smem_u32(smf);

    float acc[2][8][4];
#pragma unroll
    for (int mt = 0; mt < 2; mt++)
#pragma unroll
        for (int nt = 0; nt < 8; nt++)
#pragma unroll
            for (int q = 0; q < 4; q++) acc[mt][nt][q] = 0.f;

    auto srcs = [&](int c, const float *&sa, int &stA, const float *&sb, int &stB) {
        if (MODE == 1) {
            if (c < 4) {
                sa = g_basis2 + (size_t)t0 * 128 + c * 32;               stA = 128;
                sb = g_cvt + (size_t)b * 32768 + (size_t)n0 * 128 + c * 32; stB = 128;
            } else {
                sa = u + ((size_t)b * S + t0) * 256 + (c - 4) * 32;      stA = 256;
                sb = skw + (size_t)n0 * 256 + (c - 4) * 32;              stB = 256;
            }
        } else if (MODE == 2) {
            sa = g_act + ((size_t)b * S + t0) * 256 + c * 32;            stA = 256;
            sb = w1 + (size_t)n0 * 256 + c * 32;                         stB = 256;
        } else {
            sa = g_h + ((size_t)b * S + t0) * 128 + c * 32;              stA = 128;
            sb = w2 + (size_t)n0 * 128 + c * 32;                         stB = 128;
        }
    };

    {
        const float *sa, *sb; int stA, stB;
        srcs(0, sa, stA, sb, stB);
        stage_tile(s0, sa, stA);
        stage_tile(s0 + 128 * ROWP * 4, sb, stB);
        asm volatile("cp.async.commit_group;" ::: "memory");
    }

    for (int c = 0; c < NC; c++) {
        int buf = c & 1;
        if (c + 1 < NC) {
            const float *sa, *sb; int stA, stB;
            srcs(c + 1, sa, stA, sb, stB);
            uint32_t nb = s0 + (uint32_t)(((c + 1) & 1) * BUF_FLOATS) * 4u;
            stage_tile(nb, sa, stA);
            stage_tile(nb + 128 * ROWP * 4, sb, stB);
            asm volatile("cp.async.commit_group;" ::: "memory");
            asm volatile("cp.async.wait_group 1;" ::: "memory");
        } else {
            asm volatile("cp.async.wait_group 0;" ::: "memory");
        }
        __syncthreads();

        const float *As = smf + buf * BUF_FLOATS;
        const float *Bs = As + 128 * ROWP;
#pragma unroll
        for (int k8 = 0; k8 < 4; k8++) {
            int k0 = k8 * 8;
            uint32_t af[2][4];
#pragma unroll
            for (int mt = 0; mt < 2; mt++) {
                int r = wm * 32 + mt * 16 + g;
                af[mt][0] = tf32u(As[r * ROWP + k0 + tig]);
                af[mt][1] = tf32u(As[(r + 8) * ROWP + k0 + tig]);
                af[mt][2] = tf32u(As[r * ROWP + k0 + tig + 4]);
                af[mt][3] = tf32u(As[(r + 8) * ROWP + k0 + tig + 4]);
            }
#pragma unroll
            for (int nt = 0; nt < 8; nt++) {
                int br = wn * 64 + nt * 8 + g;
                uint32_t b0 = tf32u(Bs[br * ROWP + k0 + tig]);
                uint32_t b1 = tf32u(Bs[br * ROWP + k0 + tig + 4]);
#pragma unroll
                for (int mt = 0; mt < 2; mt++)
                    mma_tf32(acc[mt][nt], af[mt][0], af[mt][1], af[mt][2], af[mt][3], b0, b1);
            }
        }
        __syncthreads();
    }

    const float *bias = (MODE == 1) ? skb : (MODE == 2) ? b1 : b2;
    float *dst; int dstride;
    if (MODE == 1) { dst = g_act + ((size_t)b * S) * 256; dstride = 256; }
    else if (MODE == 2) { dst = g_h; dstride = 128; }
    else { dst = out + ((size_t)b * S) * 256; dstride = 256; }

#pragma unroll
    for (int mt = 0; mt < 2; mt++) {
#pragma unroll
        for (int nt = 0; nt < 8; nt++) {
            int row = t0 + wm * 32 + mt * 16 + g;
            int col = n0 + wn * 64 + nt * 8 + 2 * tig;
            float bz0 = __ldg(bias + col), bz1 = __ldg(bias + col + 1);
            float v0 = acc[mt][nt][0] + bz0, v1 = acc[mt][nt][1] + bz1;
            float v2 = acc[mt][nt][2] + bz0, v3 = acc[mt][nt][3] + bz1;
            if (MODE != 3) {
                v0 = tf32r(gelu(v0)); v1 = tf32r(gelu(v1));
                v2 = tf32r(gelu(v2)); v3 = tf32r(gelu(v3));
            }
            *(float2 *)(dst + (size_t)row * dstride + col) = make_float2(v0, v1);
            *(float2 *)(dst + (size_t)(row + 8) * dstride + col) = make_float2(v2, v3);
        }
    }
}

// ---------------- fused G2+G3: h in smem ----------------
// smem floats: hsm[64*132]@0, bufA 2x64*36 @8448, bufB 2x128*36 @13056; total 22272 floats.
#define F23_SMEM (22272 * 4)

__global__ void __launch_bounds__(256, 2) k_fused23(
    const float *__restrict__ w1, const float *__restrict__ b1,
    const float *__restrict__ w2, const float *__restrict__ b2,
    float *__restrict__ out) {
    extern __shared__ __align__(16) float smf[];
    float *hsm  = smf;
    float *bufA = smf + 8448;
    float *bufB = smf + 13056;
    uint32_t sA = smem_u32(bufA), sB = smem_u32(bufB);

    int tid = threadIdx.x, lane = tid & 31, w = tid >> 5;
    int wm = w & 1, wn = w >> 1;            // 2 (m) x 4 (n)
    int g = lane >> 2, tg = lane & 3;
    int t0 = blockIdx.x * 64, b = blockIdx.y;

    // ---------- G2: h = gelu(act @ w1^T + b1) ----------
    auto stageA2 = [&](int c, int buf) {
#pragma unroll
        for (int it = 0; it < 2; it++) {
            int v = it * 256 + tid; int r = v >> 3, j = v & 7;
            CPA16(sA + (uint32_t)(buf * 2304 + r * 36 + j * 4) * 4u,
                  g_act + ((size_t)(b * S + t0 + r)) * 256 + c * 32 + j * 4);
        }
    };
    auto stageB2 = [&](int c, int buf) {
#pragma unroll
        for (int it = 0; it < 4; it++) {
            int v = it * 256 + tid; int r = v >> 3, j = v & 7;
            CPA16(sB + (uint32_t)(buf * 4608 + r * 36 + j * 4) * 4u,
                  w1 + (size_t)r * 256 + c * 32 + j * 4);
        }
    };

    float acc[2][4][4];
#pragma unroll
    for (int mt = 0; mt < 2; mt++)
#pragma unroll
        for (int nt = 0; nt < 4; nt++)
#pragma unroll
            for (int q = 0; q < 4; q++) acc[mt][nt][q] = 0.f;

    stageA2(0, 0); stageB2(0, 0);
    asm volatile("cp.async.commit_group;" ::: "memory");
    for (int c = 0; c < 8; c++) {
        int buf = c & 1;
        if (c < 7) {
            stageA2(c + 1, buf ^ 1); stageB2(c + 1, buf ^ 1);
            asm volatile("cp.async.commit_group;" ::: "memory");
            asm volatile("cp.async.wait_group 1;" ::: "memory");
        } else {
            asm volatile("cp.async.wait_group 0;" ::: "memory");
        }
        __syncthreads();
        const float *As = bufA + buf * 2304;
        const float *Bs = bufB + buf * 4608;
#pragma unroll
        for (int k8 = 0; k8 < 4; k8++) {
            int k0 = k8 * 8;
            uint32_t af[2][4];
#pragma unroll
            for (int mt = 0; mt < 2; mt++) {
                int r = wm * 32 + mt * 16 + g;
                af[mt][0] = __float_as_uint(As[r * 36 + k0 + tg]);          // act already tf32
                af[mt][1] = __float_as_uint(As[(r + 8) * 36 + k0 + tg]);
                af[mt][2] = __float_as_uint(As[r * 36 + k0 + tg + 4]);
                af[mt][3] = __float_as_uint(As[(r + 8) * 36 + k0 + tg + 4]);
            }
#pragma unroll
            for (int nt = 0; nt < 4; nt++) {
                int br = wn * 32 + nt * 8 + g;
                uint32_t b0 = tf32u(Bs[br * 36 + k0 + tg]);
                uint32_t b1 = tf32u(Bs[br * 36 + k0 + tg + 4]);
#pragma unroll
                for (int mt = 0; mt < 2; mt++)
                    mma_tf32(acc[mt][nt], af[mt][0], af[mt][1], af[mt][2], af[mt][3], b0, b1);
            }
        }
        __syncthreads();
    }
    // epilogue G2 -> hsm
#pragma unroll
    for (int mt = 0; mt < 2; mt++)
#pragma unroll
        for (int nt = 0; nt < 4; nt++) {
            int row = wm * 32 + mt * 16 + g;
            int col = wn * 32 + nt * 8 + 2 * tg;
            float bz0 = __ldg(b1 + col), bz1 = __ldg(b1 + col + 1);
            hsm[row * 132 + col]           = tf32r(gelu(acc[mt][nt][0] + bz0));
            hsm[row * 132 + col + 1]       = tf32r(gelu(acc[mt][nt][1] + bz1));
            hsm[(row + 8) * 132 + col]     = tf32r(gelu(acc[mt][nt][2] + bz0));
            hsm[(row + 8) * 132 + col + 1] = tf32r(gelu(acc[mt][nt][3] + bz1));
        }
    __syncthreads();

    // ---------- G3: out = h @ w2^T + b2, two 128-col halves ----------
    for (int nh = 0; nh < 2; nh++) {
        auto stageW2 = [&](int c, int buf) {
#pragma unroll
            for (int it = 0; it < 4; it++) {
                int v = it * 256 + tid; int r = v >> 3, j = v & 7;
                CPA16(sB + (uint32_t)(buf * 4608 + r * 36 + j * 4) * 4u,
                      w2 + (size_t)(nh * 128 + r) * 128 + c * 32 + j * 4);
            }
        };
#pragma unroll
        for (int mt = 0; mt < 2; mt++)
#pragma unroll
            for (int nt = 0; nt < 4; nt++)
#pragma unroll
                for (int q = 0; q < 4; q++) acc[mt][nt][q] = 0.f;

        stageW2(0, 0);
        asm volatile("cp.async.commit_group;" ::: "memory");
        for (int c = 0; c < 4; c++) {
            int buf = c & 1;
            if (c < 3) {
                stageW2(c + 1, buf ^ 1);
                asm volatile("cp.async.commit_group;" ::: "memory");
                asm volatile("cp.async.wait_group 1;" ::: "memory");
            } else {
                asm volatile("cp.async.wait_group 0;" ::: "memory");
            }
            __syncthreads();
            const float *Bs = bufB + buf * 4608;
#pragma unroll
            for (int k8 = 0; k8 < 4; k8++) {
                int k0 = c * 32 + k8 * 8;      // hsm k index
                int ks = k8 * 8;               // staged w2 k index
                uint32_t af[2][4];
#pragma unroll
                for (int mt = 0; mt < 2; mt++) {
                    int r = wm * 32 + mt * 16 + g;
                    af[mt][0] = __float_as_uint(hsm[r * 132 + k0 + tg]);
                    af[mt][1] = __float_as_uint(hsm[(r + 8) * 132 + k0 + tg]);
                    af[mt][2] = __float_as_uint(hsm[r * 132 + k0 + tg + 4]);
                    af[mt][3] = __float_as_uint(hsm[(r + 8) * 132 + k0 + tg + 4]);
                }
#pragma unroll
                for (int nt = 0; nt < 4; nt++) {
                    int br = wn * 32 + nt * 8 + g;
                    uint32_t b0 = tf32u(Bs[br * 36 + ks + tg]);
                    uint32_t b1 = tf32u(Bs[br * 36 + ks + tg + 4]);
#pragma unroll
                    for (int mt = 0; mt < 2; mt++)
                        mma_tf32(acc[mt][nt], af[mt][0], af[mt][1], af[mt][2], af[mt][3], b0, b1);
                }
            }
            __syncthreads();
        }
        // epilogue G3 -> out
#pragma unroll
        for (int mt = 0; mt < 2; mt++)
#pragma unroll
            for (int nt = 0; nt < 4; nt++) {
                int row = t0 + wm * 32 + mt * 16 + g;
                int col = nh * 128 + wn * 32 + nt * 8 + 2 * tg;
                float bz0 = __ldg(b2 + col), bz1 = __ldg(b2 + col + 1);
                float2 v0 = make_float2(acc[mt][nt][0] + bz0, acc[mt][nt][1] + bz1);
                float2 v1 = make_float2(acc[mt][nt][2] + bz0, acc[mt][nt][3] + bz1);
                *(float2 *)(out + ((size_t)b * S + row) * 256 + col)     = v0;
                *(float2 *)(out + ((size_t)b * S + row + 8) * 256 + col) = v1;
            }
        __syncthreads();
    }
}

// ---------------- launch ----------------
extern "C" void kernel_launch(void *const *d_in, const int *in_sizes, int n_in,
                              void *d_out, int out_size) {
    const float *u   = (const float *)d_in[0];
    const float *Wr  = (const float *)d_in[1];
    const float *Wi  = (const float *)d_in[2];
    const float *skw = (const float *)d_in[3];
    const float *skb = (const float *)d_in[4];
    const float *w1  = (const float *)d_in[5];
    const float *b1  = (const float *)d_in[6];
    const float *w2  = (const float *)d_in[7];
    const float *b2  = (const float *)d_in[8];
    float *out = (float *)d_out;

    cudaFuncSetAttribute(k_dftmma, cudaFuncAttributeMaxDynamicSharedMemorySize, DFT_SMEM);
    cudaFuncSetAttribute(k_gemm<1>, cudaFuncAttributeMaxDynamicSharedMemorySize, GEMM_SMEM_BYTES);
    cudaFuncSetAttribute(k_fused23, cudaFuncAttributeMaxDynamicSharedMemorySize, F23_SMEM);

    k_phase<<<(S + 255) / 256, 256>>>();
    k_basisF<<<(128 * S) / 256, 256>>>();
    k_basis2<<<(S * 128 + 255) / 256, 256>>>();
    k_usplit<<<(B * S * H / 4) / 256, 256>>>(u);
    k_dftmma<<<dim3(DFT_KS, 2, B), 256, DFT_SMEM>>>();
    k_dftred<<<(B * 128 * 256) / 256, 256>>>();
    k_modegemm<<<dim3(M, 2, 4), 256>>>(Wr, Wi);
    k_mgred<<<(B * M * H) / 256, 256>>>();
    k_conv<<<dim3(B, 8), 256>>>();
    k_gemm<1><<<dim3(64, 2, B), 256, GEMM_SMEM_BYTES>>>(u, skw, skb, w1, b1, w2, b2, out);
    k_fused23<<<dim3(S / 64, B), 256, F23_SMEM>>>(w1, b1, w2, b2, out);
}